// round 6
// baseline (speedup 1.0000x reference)
#include <cuda_runtime.h>

#define D_MODEL 1024
#define NHEAD 16
#define DEPTH 64
#define BB 2
#define SEQ 2048
#define MTOT (BB * SEQ)  // 4096

// Scratch (allocation-free rule: __device__ globals)
__device__ float g_qh[(size_t)BB * NHEAD * SEQ * DEPTH];  // [B,H,S,64]
__device__ float g_kh[(size_t)BB * NHEAD * SEQ * DEPTH];
__device__ float g_vh[(size_t)BB * NHEAD * SEQ * DEPTH];
__device__ float g_att[(size_t)MTOT * D_MODEL];           // [B,S,1024] merged heads

// ---------------------------------------------------------------------------
// 128x128x8 fp32 SGEMM body: Y = X @ W + bias.  M=4096, N=K=1024.
// split=true  -> write head-split layout [B,H,S,64]
// split=false -> write row-major [M,N]
// ---------------------------------------------------------------------------
__device__ __forceinline__ void gemm_body(
    const float* __restrict__ X, const float* __restrict__ W,
    const float* __restrict__ bias, float* __restrict__ Y, bool split)
{
    __shared__ __align__(16) float As[8][132];  // transposed A tile, pad -> conflict-free
    __shared__ __align__(16) float Bs[8][128];

    const int K = D_MODEL, N = D_MODEL;
    const int m0 = blockIdx.y * 128;
    const int n0 = blockIdx.x * 128;
    const int tid = threadIdx.x;
    const int tx = tid & 15;
    const int ty = tid >> 4;
    const int arow = tid >> 1;          // 0..127
    const int acol = (tid & 1) * 4;     // 0 or 4
    const int brow = tid >> 5;          // 0..7
    const int bcol = (tid & 31) * 4;    // 0..124

    const float* xp = X + (size_t)(m0 + arow) * K + acol;
    const float* wp = W + (size_t)brow * N + n0 + bcol;

    float acc[8][8];
#pragma unroll
    for (int i = 0; i < 8; ++i)
#pragma unroll
        for (int j = 0; j < 8; ++j) acc[i][j] = 0.f;

    for (int t = 0; t < K / 8; ++t) {
        float4 av = *(const float4*)xp;
        float4 bv = *(const float4*)wp;
        __syncthreads();
        As[acol + 0][arow] = av.x;
        As[acol + 1][arow] = av.y;
        As[acol + 2][arow] = av.z;
        As[acol + 3][arow] = av.w;
        *(float4*)&Bs[brow][bcol] = bv;
        __syncthreads();
#pragma unroll
        for (int kk = 0; kk < 8; ++kk) {
            float a[8], b[8];
            *(float4*)&a[0] = *(const float4*)&As[kk][ty * 8];
            *(float4*)&a[4] = *(const float4*)&As[kk][ty * 8 + 4];
            *(float4*)&b[0] = *(const float4*)&Bs[kk][tx * 8];
            *(float4*)&b[4] = *(const float4*)&Bs[kk][tx * 8 + 4];
#pragma unroll
            for (int i = 0; i < 8; ++i)
#pragma unroll
                for (int j = 0; j < 8; ++j)
                    acc[i][j] += a[i] * b[j];
        }
        xp += 8;
        wp += (size_t)8 * N;
    }

#pragma unroll
    for (int i = 0; i < 8; ++i) {
        int m = m0 + ty * 8 + i;
        int bb = m >> 11;          // m / SEQ
        int sq = m & (SEQ - 1);
#pragma unroll
        for (int j0 = 0; j0 < 8; j0 += 4) {
            int n = n0 + tx * 8 + j0;
            float4 o;
            o.x = acc[i][j0 + 0] + bias[n + 0];
            o.y = acc[i][j0 + 1] + bias[n + 1];
            o.z = acc[i][j0 + 2] + bias[n + 2];
            o.w = acc[i][j0 + 3] + bias[n + 3];
            if (split) {
                int h = n >> 6;
                int d = n & 63;    // multiple of 4, stays within head
                *(float4*)&Y[(((size_t)bb * NHEAD + h) * SEQ + sq) * DEPTH + d] = o;
            } else {
                *(float4*)&Y[(size_t)m * N + n] = o;
            }
        }
    }
}

__global__ __launch_bounds__(256) void qkv_proj_kernel(
    const float* __restrict__ q, const float* __restrict__ k, const float* __restrict__ v,
    const float* __restrict__ wq, const float* __restrict__ wk, const float* __restrict__ wv,
    const float* __restrict__ bq, const float* __restrict__ bk, const float* __restrict__ bv)
{
    if (blockIdx.z == 0)      gemm_body(q, wq, bq, g_qh, true);
    else if (blockIdx.z == 1) gemm_body(k, wk, bk, g_kh, true);
    else                      gemm_body(v, wv, bv, g_vh, true);
}

__global__ __launch_bounds__(256) void out_proj_kernel(
    const float* __restrict__ wo, const float* __restrict__ bo, float* __restrict__ out)
{
    gemm_body(g_att, wo, bo, out, false);
}

// ---------------------------------------------------------------------------
// Flash attention: 64 q-rows per CTA, 32 k-tiles of 64, online softmax.
// Threads: 256 as 16x16; each thread owns 4 q-rows x 4 cols.
// Dyn smem: Qs[64][65] + Ks[64][65] + Vs[64][64] = 49664 B
// ---------------------------------------------------------------------------
__global__ __launch_bounds__(256) void flash_attn_kernel(const float* __restrict__ mask)
{
    extern __shared__ float sm[];
    float* Qs = sm;                 // [64][65]
    float* Ks = sm + 64 * 65;       // [64][65]
    float* Vs = sm + 2 * 64 * 65;   // [64][64]

    const int bh = blockIdx.y;                 // 0..31 (= b*16 + h)
    const int q0 = blockIdx.x * 64;
    const float* Qp = g_qh + (size_t)bh * SEQ * DEPTH;
    const float* Kp = g_kh + (size_t)bh * SEQ * DEPTH;
    const float* Vp = g_vh + (size_t)bh * SEQ * DEPTH;

    const int tid = threadIdx.x;
    const int tx = tid & 15;
    const int ty = tid >> 4;
    const int lrow = tid >> 4;       // 0..15 (load helper)
    const int lc4 = (tid & 15) * 4;  // 0..60

    // Load Q tile (64x64) into padded smem
#pragma unroll
    for (int r = 0; r < 4; ++r) {
        int rr = lrow + r * 16;
        float4 qv = *(const float4*)&Qp[(size_t)(q0 + rr) * DEPTH + lc4];
        Qs[rr * 65 + lc4 + 0] = qv.x;
        Qs[rr * 65 + lc4 + 1] = qv.y;
        Qs[rr * 65 + lc4 + 2] = qv.z;
        Qs[rr * 65 + lc4 + 3] = qv.w;
    }

    float m_i[4], l_i[4], acc[4][4];
#pragma unroll
    for (int i = 0; i < 4; ++i) {
        m_i[i] = -1e30f;
        l_i[i] = 0.f;
#pragma unroll
        for (int j = 0; j < 4; ++j) acc[i][j] = 0.f;
    }
    const float scale = 0.125f;  // 1/sqrt(64)

    for (int kt = 0; kt < SEQ / 64; ++kt) {
        const int k0 = kt * 64;
        __syncthreads();  // prior iteration done reading Ks/Vs
#pragma unroll
        for (int r = 0; r < 4; ++r) {
            int rr = lrow + r * 16;
            float4 kv = *(const float4*)&Kp[(size_t)(k0 + rr) * DEPTH + lc4];
            Ks[rr * 65 + lc4 + 0] = kv.x;
            Ks[rr * 65 + lc4 + 1] = kv.y;
            Ks[rr * 65 + lc4 + 2] = kv.z;
            Ks[rr * 65 + lc4 + 3] = kv.w;
            float4 vv = *(const float4*)&Vp[(size_t)(k0 + rr) * DEPTH + lc4];
            *(float4*)&Vs[rr * 64 + lc4] = vv;
        }
        __syncthreads();

        // Scores: s[i][j] = Q[row_i] . K[col_j]
        float s[4][4];
#pragma unroll
        for (int i = 0; i < 4; ++i)
#pragma unroll
            for (int j = 0; j < 4; ++j) s[i][j] = 0.f;

#pragma unroll 8
        for (int dd = 0; dd < 64; ++dd) {
            float qv[4], kv[4];
#pragma unroll
            for (int i = 0; i < 4; ++i) qv[i] = Qs[(ty * 4 + i) * 65 + dd];
#pragma unroll
            for (int j = 0; j < 4; ++j) kv[j] = Ks[(tx * 4 + j) * 65 + dd];
#pragma unroll
            for (int i = 0; i < 4; ++i)
#pragma unroll
                for (int j = 0; j < 4; ++j)
                    s[i][j] += qv[i] * kv[j];
        }

        // Scale + mask + online softmax update
#pragma unroll
        for (int i = 0; i < 4; ++i) {
            const int qrow = q0 + ty * 4 + i;
            float4 mv = *(const float4*)&mask[(size_t)qrow * SEQ + k0 + tx * 4];
            s[i][0] = s[i][0] * scale - 1e9f * mv.x;
            s[i][1] = s[i][1] * scale - 1e9f * mv.y;
            s[i][2] = s[i][2] * scale - 1e9f * mv.z;
            s[i][3] = s[i][3] * scale - 1e9f * mv.w;

            float mx = fmaxf(fmaxf(s[i][0], s[i][1]), fmaxf(s[i][2], s[i][3]));
            mx = fmaxf(mx, __shfl_xor_sync(0xffffffffu, mx, 1, 16));
            mx = fmaxf(mx, __shfl_xor_sync(0xffffffffu, mx, 2, 16));
            mx = fmaxf(mx, __shfl_xor_sync(0xffffffffu, mx, 4, 16));
            mx = fmaxf(mx, __shfl_xor_sync(0xffffffffu, mx, 8, 16));

            float mn = fmaxf(m_i[i], mx);
            float corr = __expf(m_i[i] - mn);
            m_i[i] = mn;

            float rs = 0.f;
#pragma unroll
            for (int j = 0; j < 4; ++j) {
                s[i][j] = __expf(s[i][j] - mn);   // s now holds P
                rs += s[i][j];
            }
            rs += __shfl_xor_sync(0xffffffffu, rs, 1, 16);
            rs += __shfl_xor_sync(0xffffffffu, rs, 2, 16);
            rs += __shfl_xor_sync(0xffffffffu, rs, 4, 16);
            rs += __shfl_xor_sync(0xffffffffu, rs, 8, 16);

            l_i[i] = l_i[i] * corr + rs;
#pragma unroll
            for (int j = 0; j < 4; ++j) acc[i][j] *= corr;
        }

        // PV: acc[i][d] += P[i][kk] * V[kk][d], P broadcast via shuffle
#pragma unroll 4
        for (int k4 = 0; k4 < 16; ++k4) {
#pragma unroll
            for (int sub = 0; sub < 4; ++sub) {
                const int kk = k4 * 4 + sub;
                float4 vv = *(const float4*)&Vs[kk * 64 + tx * 4];
                float p0 = __shfl_sync(0xffffffffu, s[0][sub], k4, 16);
                float p1 = __shfl_sync(0xffffffffu, s[1][sub], k4, 16);
                float p2 = __shfl_sync(0xffffffffu, s[2][sub], k4, 16);
                float p3 = __shfl_sync(0xffffffffu, s[3][sub], k4, 16);
                acc[0][0] += p0 * vv.x; acc[0][1] += p0 * vv.y; acc[0][2] += p0 * vv.z; acc[0][3] += p0 * vv.w;
                acc[1][0] += p1 * vv.x; acc[1][1] += p1 * vv.y; acc[1][2] += p1 * vv.z; acc[1][3] += p1 * vv.w;
                acc[2][0] += p2 * vv.x; acc[2][1] += p2 * vv.y; acc[2][2] += p2 * vv.z; acc[2][3] += p2 * vv.w;
                acc[3][0] += p3 * vv.x; acc[3][1] += p3 * vv.y; acc[3][2] += p3 * vv.z; acc[3][3] += p3 * vv.w;
            }
        }
    }

    // Epilogue: normalize, write merged-head layout [B,S,1024]
    const int bb = bh >> 4;
    const int h = bh & 15;
#pragma unroll
    for (int i = 0; i < 4; ++i) {
        float inv = 1.f / l_i[i];
        int sq = q0 + ty * 4 + i;
        float4 o;
        o.x = acc[i][0] * inv;
        o.y = acc[i][1] * inv;
        o.z = acc[i][2] * inv;
        o.w = acc[i][3] * inv;
        *(float4*)&g_att[((size_t)bb * SEQ + sq) * D_MODEL + h * DEPTH + tx * 4] = o;
    }
}

// ---------------------------------------------------------------------------
extern "C" void kernel_launch(void* const* d_in, const int* in_sizes, int n_in,
                              void* d_out, int out_size)
{
    const float* q    = (const float*)d_in[0];
    const float* k    = (const float*)d_in[1];
    const float* v    = (const float*)d_in[2];
    const float* mask = (const float*)d_in[3];
    const float* wq   = (const float*)d_in[4];
    const float* bq   = (const float*)d_in[5];
    const float* wk   = (const float*)d_in[6];
    const float* bk   = (const float*)d_in[7];
    const float* wv   = (const float*)d_in[8];
    const float* bv   = (const float*)d_in[9];
    const float* wo   = (const float*)d_in[10];
    const float* bo   = (const float*)d_in[11];
    float* out = (float*)d_out;

    (void)in_sizes; (void)n_in; (void)out_size;

    cudaFuncSetAttribute(flash_attn_kernel,
                         cudaFuncAttributeMaxDynamicSharedMemorySize, 49664);

    dim3 gproj(D_MODEL / 128, MTOT / 128, 3);   // (8, 32, 3) = 768 CTAs
    qkv_proj_kernel<<<gproj, 256>>>(q, k, v, wq, wk, wv, bq, bk, bv);

    flash_attn_kernel<<<dim3(SEQ / 64, BB * NHEAD), 256, 49664>>>(mask);

    out_proj_kernel<<<dim3(D_MODEL / 128, MTOT / 128), 256>>>(wo, bo, out);
}

// round 9
// speedup vs baseline: 1.4771x; 1.4771x over previous
#include <cuda_runtime.h>
#include <cstdint>

#define D_MODEL 1024
#define NHEAD 16
#define DEPTH 64
#define BB 2
#define SEQ 2048
#define MTOT (BB * SEQ)  // 4096

// Scratch (allocation-free rule: __device__ globals)
__device__ float g_qh[(size_t)BB * NHEAD * SEQ * DEPTH];  // [B,H,S,64]
__device__ float g_kh[(size_t)BB * NHEAD * SEQ * DEPTH];
__device__ float g_vh[(size_t)BB * NHEAD * SEQ * DEPTH];
__device__ float g_att[(size_t)MTOT * D_MODEL];           // [B,S,1024] merged heads

// ===========================================================================
// tf32 tensor-core GEMM: Y = X @ W + bias.  M=4096, N=K=1024.
// CTA tile 128x128, K-chunk 32, 8 warps (2x4), warp tile 64x32.
// mma.sync.aligned.m16n8k8.row.col.f32.tf32.tf32.f32
// ===========================================================================
#define BKK 32
#define ASTR 36    // As[m][k] row stride (floats): frag a0 bank = (4g+t)%32, conflict-free
#define BSTR 136   // Bs[k][n] row stride (floats): frag b0 bank = (8t+g)%32, conflict-free
#define PERBUF (128 * ASTR + BKK * BSTR)   // 4608 + 4352 = 8960 words per buffer
#define GEMM_SMEM (2 * PERBUF * 4)         // 71680 bytes

__device__ __forceinline__ uint32_t f2tf(float f) {
    uint32_t u;
    asm("cvt.rna.tf32.f32 %0, %1;" : "=r"(u) : "f"(f));
    return u;
}

__device__ __forceinline__ void mma_tf32(float& c0, float& c1, float& c2, float& c3,
                                         uint32_t a0, uint32_t a1, uint32_t a2, uint32_t a3,
                                         uint32_t b0, uint32_t b1) {
    asm("mma.sync.aligned.m16n8k8.row.col.f32.tf32.tf32.f32 "
        "{%0,%1,%2,%3},{%4,%5,%6,%7},{%8,%9},{%0,%1,%2,%3};"
        : "+f"(c0), "+f"(c1), "+f"(c2), "+f"(c3)
        : "r"(a0), "r"(a1), "r"(a2), "r"(a3), "r"(b0), "r"(b1));
}

__device__ __forceinline__ void gemm_tf32_body(
    const float* __restrict__ X, const float* __restrict__ W,
    const float* __restrict__ bias, float* __restrict__ Y, bool split)
{
    extern __shared__ uint32_t smu[];

    const int K = D_MODEL, N = D_MODEL;
    const int m0 = blockIdx.y * 128;
    const int n0 = blockIdx.x * 128;
    const int tid = threadIdx.x;
    const int lane = tid & 31;
    const int wid = tid >> 5;
    const int warpM = wid >> 2;          // 0..1 -> rows warpM*64
    const int warpN = wid & 3;           // 0..3 -> cols warpN*32
    const int g = lane >> 2;             // groupID 0..7
    const int t = lane & 3;              // thread-in-group 0..3

    // gmem staging pointers
    // A: 8 lanes cover one row's 32-float chunk (128B coalesced)
    const float* xp = X + (size_t)(m0 + (tid >> 3)) * K + (tid & 7) * 4;
    // B: warp covers one k-row's 128-float chunk (512B coalesced)
    const float* wp = W + (size_t)(tid >> 5) * N + n0 + (tid & 31) * 4;

    const int aOff = (tid >> 3) * ASTR + (tid & 7) * 4;   // + i*32*ASTR
    const int bOff = (tid >> 5) * BSTR + (tid & 31) * 4;  // + i*8*BSTR

    float acc[4][4][4];
#pragma unroll
    for (int mt = 0; mt < 4; ++mt)
#pragma unroll
        for (int nt = 0; nt < 4; ++nt)
#pragma unroll
            for (int r = 0; r < 4; ++r) acc[mt][nt][r] = 0.f;

    float4 ra[4], rb[4];

    // prologue: stage tile 0
#pragma unroll
    for (int i = 0; i < 4; ++i) {
        ra[i] = *(const float4*)(xp + (size_t)i * 32 * K);
        rb[i] = *(const float4*)(wp + (size_t)i * 8 * N);
    }
    {
        uint32_t* Au = smu;
        uint32_t* Bu = smu + 128 * ASTR;
#pragma unroll
        for (int i = 0; i < 4; ++i) {
            uint32_t* ap = Au + aOff + i * 32 * ASTR;
            uint2 p0 = make_uint2(f2tf(ra[i].x), f2tf(ra[i].y));
            uint2 p1 = make_uint2(f2tf(ra[i].z), f2tf(ra[i].w));
            *(uint2*)(ap + 0) = p0;
            *(uint2*)(ap + 2) = p1;
            uint4 q = make_uint4(f2tf(rb[i].x), f2tf(rb[i].y), f2tf(rb[i].z), f2tf(rb[i].w));
            *(uint4*)(Bu + bOff + i * 8 * BSTR) = q;
        }
    }
    __syncthreads();

    const int NKT = K / BKK;   // 32
    for (int kt = 0; kt < NKT; ++kt) {
        if (kt + 1 < NKT) {
#pragma unroll
            for (int i = 0; i < 4; ++i) {
                ra[i] = *(const float4*)(xp + (kt + 1) * BKK + (size_t)i * 32 * K);
                rb[i] = *(const float4*)(wp + ((size_t)(kt + 1) * BKK + i * 8) * N);
            }
        }

        // compute on buffer kt&1
        {
            const uint32_t* Au = smu + (kt & 1) * PERBUF;
            const uint32_t* Bu = Au + 128 * ASTR;
            const int mBase = warpM * 64 + g;
            const int nBase = warpN * 32 + g;
#pragma unroll
            for (int ks = 0; ks < 4; ++ks) {
                const int k0 = ks * 8;
                uint32_t af[4][4], bf[4][2];
#pragma unroll
                for (int mt = 0; mt < 4; ++mt) {
                    const uint32_t* base = Au + (mBase + mt * 16) * ASTR + k0 + t;
                    af[mt][0] = base[0];
                    af[mt][1] = base[8 * ASTR];
                    af[mt][2] = base[4];
                    af[mt][3] = base[8 * ASTR + 4];
                }
#pragma unroll
                for (int nt = 0; nt < 4; ++nt) {
                    const uint32_t* base = Bu + (k0 + t) * BSTR + nBase + nt * 8;
                    bf[nt][0] = base[0];
                    bf[nt][1] = base[4 * BSTR];
                }
#pragma unroll
                for (int mt = 0; mt < 4; ++mt)
#pragma unroll
                    for (int nt = 0; nt < 4; ++nt)
                        mma_tf32(acc[mt][nt][0], acc[mt][nt][1], acc[mt][nt][2], acc[mt][nt][3],
                                 af[mt][0], af[mt][1], af[mt][2], af[mt][3],
                                 bf[nt][0], bf[nt][1]);
            }
        }

        if (kt + 1 < NKT) {
            uint32_t* Au = smu + ((kt + 1) & 1) * PERBUF;
            uint32_t* Bu = Au + 128 * ASTR;
#pragma unroll
            for (int i = 0; i < 4; ++i) {
                uint32_t* ap = Au + aOff + i * 32 * ASTR;
                uint2 p0 = make_uint2(f2tf(ra[i].x), f2tf(ra[i].y));
                uint2 p1 = make_uint2(f2tf(ra[i].z), f2tf(ra[i].w));
                *(uint2*)(ap + 0) = p0;
                *(uint2*)(ap + 2) = p1;
                uint4 q = make_uint4(f2tf(rb[i].x), f2tf(rb[i].y), f2tf(rb[i].z), f2tf(rb[i].w));
                *(uint4*)(Bu + bOff + i * 8 * BSTR) = q;
            }
        }
        __syncthreads();
    }

    // Epilogue: c0=(g,2t) c1=(g,2t+1) c2=(g+8,2t) c3=(g+8,2t+1)
#pragma unroll
    for (int mt = 0; mt < 4; ++mt) {
#pragma unroll
        for (int nt = 0; nt < 4; ++nt) {
            const int m = m0 + warpM * 64 + mt * 16 + g;
            const int n = n0 + warpN * 32 + nt * 8 + 2 * t;
            const float b0v = bias[n], b1v = bias[n + 1];
            float2 lo = make_float2(acc[mt][nt][0] + b0v, acc[mt][nt][1] + b1v);
            float2 hi = make_float2(acc[mt][nt][2] + b0v, acc[mt][nt][3] + b1v);
            if (split) {
                const int h = n >> 6;
                const int d = n & 63;   // even
                const int bb = m >> 11;
                const int sq = m & (SEQ - 1);
                float* p = g_qh; // placeholder, overwritten via Y below
                (void)p;
                float* y0 = Y + (((size_t)bb * NHEAD + h) * SEQ + sq) * DEPTH + d;
                *(float2*)y0 = lo;
                const int m2 = m + 8;
                const int bb2 = m2 >> 11;
                const int sq2 = m2 & (SEQ - 1);
                float* y1 = Y + (((size_t)bb2 * NHEAD + h) * SEQ + sq2) * DEPTH + d;
                *(float2*)y1 = hi;
            } else {
                *(float2*)&Y[(size_t)m * N + n] = lo;
                *(float2*)&Y[(size_t)(m + 8) * N + n] = hi;
            }
        }
    }
}

__global__ __launch_bounds__(256) void qkv_proj_kernel(
    const float* __restrict__ q, const float* __restrict__ k, const float* __restrict__ v,
    const float* __restrict__ wq, const float* __restrict__ wk, const float* __restrict__ wv,
    const float* __restrict__ bq, const float* __restrict__ bk, const float* __restrict__ bv)
{
    if (blockIdx.z == 0)      gemm_tf32_body(q, wq, bq, g_qh, true);
    else if (blockIdx.z == 1) gemm_tf32_body(k, wk, bk, g_kh, true);
    else                      gemm_tf32_body(v, wv, bv, g_vh, true);
}

__global__ __launch_bounds__(256) void out_proj_kernel(
    const float* __restrict__ wo, const float* __restrict__ bo, float* __restrict__ out)
{
    gemm_tf32_body(g_att, wo, bo, out, false);
}

// ---------------------------------------------------------------------------
// Flash attention (unchanged from R5 baseline): 64 q-rows per CTA, 32 k-tiles
// of 64, online softmax. 256 threads as 16x16; 4x4 per thread.
// Dyn smem: Qs[64][65] + Ks[64][65] + Vs[64][64] = 49664 B
// ---------------------------------------------------------------------------
__global__ __launch_bounds__(256) void flash_attn_kernel(const float* __restrict__ mask)
{
    extern __shared__ float sm[];
    float* Qs = sm;                 // [64][65]
    float* Ks = sm + 64 * 65;       // [64][65]
    float* Vs = sm + 2 * 64 * 65;   // [64][64]

    const int bh = blockIdx.y;                 // 0..31 (= b*16 + h)
    const int q0 = blockIdx.x * 64;
    const float* Qp = g_qh + (size_t)bh * SEQ * DEPTH;
    const float* Kp = g_kh + (size_t)bh * SEQ * DEPTH;
    const float* Vp = g_vh + (size_t)bh * SEQ * DEPTH;

    const int tid = threadIdx.x;
    const int tx = tid & 15;
    const int ty = tid >> 4;
    const int lrow = tid >> 4;       // 0..15 (load helper)
    const int lc4 = (tid & 15) * 4;  // 0..60

#pragma unroll
    for (int r = 0; r < 4; ++r) {
        int rr = lrow + r * 16;
        float4 qv = *(const float4*)&Qp[(size_t)(q0 + rr) * DEPTH + lc4];
        Qs[rr * 65 + lc4 + 0] = qv.x;
        Qs[rr * 65 + lc4 + 1] = qv.y;
        Qs[rr * 65 + lc4 + 2] = qv.z;
        Qs[rr * 65 + lc4 + 3] = qv.w;
    }

    float m_i[4], l_i[4], acc[4][4];
#pragma unroll
    for (int i = 0; i < 4; ++i) {
        m_i[i] = -1e30f;
        l_i[i] = 0.f;
#pragma unroll
        for (int j = 0; j < 4; ++j) acc[i][j] = 0.f;
    }
    const float scale = 0.125f;  // 1/sqrt(64)

    for (int kt = 0; kt < SEQ / 64; ++kt) {
        const int k0 = kt * 64;
        __syncthreads();
#pragma unroll
        for (int r = 0; r < 4; ++r) {
            int rr = lrow + r * 16;
            float4 kv = *(const float4*)&Kp[(size_t)(k0 + rr) * DEPTH + lc4];
            Ks[rr * 65 + lc4 + 0] = kv.x;
            Ks[rr * 65 + lc4 + 1] = kv.y;
            Ks[rr * 65 + lc4 + 2] = kv.z;
            Ks[rr * 65 + lc4 + 3] = kv.w;
            float4 vv = *(const float4*)&Vp[(size_t)(k0 + rr) * DEPTH + lc4];
            *(float4*)&Vs[rr * 64 + lc4] = vv;
        }
        __syncthreads();

        float s[4][4];
#pragma unroll
        for (int i = 0; i < 4; ++i)
#pragma unroll
            for (int j = 0; j < 4; ++j) s[i][j] = 0.f;

#pragma unroll 8
        for (int dd = 0; dd < 64; ++dd) {
            float qv[4], kv[4];
#pragma unroll
            for (int i = 0; i < 4; ++i) qv[i] = Qs[(ty * 4 + i) * 65 + dd];
#pragma unroll
            for (int j = 0; j < 4; ++j) kv[j] = Ks[(tx * 4 + j) * 65 + dd];
#pragma unroll
            for (int i = 0; i < 4; ++i)
#pragma unroll
                for (int j = 0; j < 4; ++j)
                    s[i][j] += qv[i] * kv[j];
        }

#pragma unroll
        for (int i = 0; i < 4; ++i) {
            const int qrow = q0 + ty * 4 + i;
            float4 mv = *(const float4*)&mask[(size_t)qrow * SEQ + k0 + tx * 4];
            s[i][0] = s[i][0] * scale - 1e9f * mv.x;
            s[i][1] = s[i][1] * scale - 1e9f * mv.y;
            s[i][2] = s[i][2] * scale - 1e9f * mv.z;
            s[i][3] = s[i][3] * scale - 1e9f * mv.w;

            float mx = fmaxf(fmaxf(s[i][0], s[i][1]), fmaxf(s[i][2], s[i][3]));
            mx = fmaxf(mx, __shfl_xor_sync(0xffffffffu, mx, 1, 16));
            mx = fmaxf(mx, __shfl_xor_sync(0xffffffffu, mx, 2, 16));
            mx = fmaxf(mx, __shfl_xor_sync(0xffffffffu, mx, 4, 16));
            mx = fmaxf(mx, __shfl_xor_sync(0xffffffffu, mx, 8, 16));

            float mn = fmaxf(m_i[i], mx);
            float corr = __expf(m_i[i] - mn);
            m_i[i] = mn;

            float rs = 0.f;
#pragma unroll
            for (int j = 0; j < 4; ++j) {
                s[i][j] = __expf(s[i][j] - mn);
                rs += s[i][j];
            }
            rs += __shfl_xor_sync(0xffffffffu, rs, 1, 16);
            rs += __shfl_xor_sync(0xffffffffu, rs, 2, 16);
            rs += __shfl_xor_sync(0xffffffffu, rs, 4, 16);
            rs += __shfl_xor_sync(0xffffffffu, rs, 8, 16);

            l_i[i] = l_i[i] * corr + rs;
#pragma unroll
            for (int j = 0; j < 4; ++j) acc[i][j] *= corr;
        }

#pragma unroll 4
        for (int k4 = 0; k4 < 16; ++k4) {
#pragma unroll
            for (int sub = 0; sub < 4; ++sub) {
                const int kk = k4 * 4 + sub;
                float4 vv = *(const float4*)&Vs[kk * 64 + tx * 4];
                float p0 = __shfl_sync(0xffffffffu, s[0][sub], k4, 16);
                float p1 = __shfl_sync(0xffffffffu, s[1][sub], k4, 16);
                float p2 = __shfl_sync(0xffffffffu, s[2][sub], k4, 16);
                float p3 = __shfl_sync(0xffffffffu, s[3][sub], k4, 16);
                acc[0][0] += p0 * vv.x; acc[0][1] += p0 * vv.y; acc[0][2] += p0 * vv.z; acc[0][3] += p0 * vv.w;
                acc[1][0] += p1 * vv.x; acc[1][1] += p1 * vv.y; acc[1][2] += p1 * vv.z; acc[1][3] += p1 * vv.w;
                acc[2][0] += p2 * vv.x; acc[2][1] += p2 * vv.y; acc[2][2] += p2 * vv.z; acc[2][3] += p2 * vv.w;
                acc[3][0] += p3 * vv.x; acc[3][1] += p3 * vv.y; acc[3][2] += p3 * vv.z; acc[3][3] += p3 * vv.w;
            }
        }
    }

    const int bb = bh >> 4;
    const int h = bh & 15;
#pragma unroll
    for (int i = 0; i < 4; ++i) {
        float inv = 1.f / l_i[i];
        int sq = q0 + ty * 4 + i;
        float4 o;
        o.x = acc[i][0] * inv;
        o.y = acc[i][1] * inv;
        o.z = acc[i][2] * inv;
        o.w = acc[i][3] * inv;
        *(float4*)&g_att[((size_t)bb * SEQ + sq) * D_MODEL + h * DEPTH + tx * 4] = o;
    }
}

// ---------------------------------------------------------------------------
extern "C" void kernel_launch(void* const* d_in, const int* in_sizes, int n_in,
                              void* d_out, int out_size)
{
    const float* q    = (const float*)d_in[0];
    const float* k    = (const float*)d_in[1];
    const float* v    = (const float*)d_in[2];
    const float* mask = (const float*)d_in[3];
    const float* wq   = (const float*)d_in[4];
    const float* bq   = (const float*)d_in[5];
    const float* wk   = (const float*)d_in[6];
    const float* bk   = (const float*)d_in[7];
    const float* wv   = (const float*)d_in[8];
    const float* bv   = (const float*)d_in[9];
    const float* wo   = (const float*)d_in[10];
    const float* bo   = (const float*)d_in[11];
    float* out = (float*)d_out;

    (void)in_sizes; (void)n_in; (void)out_size;

    cudaFuncSetAttribute(qkv_proj_kernel,
                         cudaFuncAttributeMaxDynamicSharedMemorySize, GEMM_SMEM);
    cudaFuncSetAttribute(out_proj_kernel,
                         cudaFuncAttributeMaxDynamicSharedMemorySize, GEMM_SMEM);
    cudaFuncSetAttribute(flash_attn_kernel,
                         cudaFuncAttributeMaxDynamicSharedMemorySize, 49664);

    dim3 gproj(D_MODEL / 128, MTOT / 128, 3);   // (8, 32, 3) = 768 CTAs
    qkv_proj_kernel<<<gproj, 256, GEMM_SMEM>>>(q, k, v, wq, wk, wv, bq, bk, bv);

    flash_attn_kernel<<<dim3(SEQ / 64, BB * NHEAD), 256, 49664>>>(mask);

    out_proj_kernel<<<dim3(D_MODEL / 128, MTOT / 128), 256, GEMM_SMEM>>>(wo, bo, out);
}

// round 11
// speedup vs baseline: 2.6345x; 1.7836x over previous
#include <cuda_runtime.h>
#include <cstdint>

#define D_MODEL 1024
#define NHEAD 16
#define DEPTH 64
#define BB 2
#define SEQ 2048
#define MTOT (BB * SEQ)  // 4096

// Scratch (allocation-free rule: __device__ globals)
__device__ float g_qh[(size_t)BB * NHEAD * SEQ * DEPTH];  // [B,H,S,64]
__device__ float g_kh[(size_t)BB * NHEAD * SEQ * DEPTH];
__device__ float g_vh[(size_t)BB * NHEAD * SEQ * DEPTH];
__device__ float g_att[(size_t)MTOT * D_MODEL];           // [B,S,1024] merged heads

__device__ __forceinline__ uint32_t f2tf(float f) {
    uint32_t u;
    asm("cvt.rna.tf32.f32 %0, %1;" : "=r"(u) : "f"(f));
    return u;
}

__device__ __forceinline__ void mma_tf32(float& c0, float& c1, float& c2, float& c3,
                                         uint32_t a0, uint32_t a1, uint32_t a2, uint32_t a3,
                                         uint32_t b0, uint32_t b1) {
    asm("mma.sync.aligned.m16n8k8.row.col.f32.tf32.tf32.f32 "
        "{%0,%1,%2,%3},{%4,%5,%6,%7},{%8,%9},{%0,%1,%2,%3};"
        : "+f"(c0), "+f"(c1), "+f"(c2), "+f"(c3)
        : "r"(a0), "r"(a1), "r"(a2), "r"(a3), "r"(b0), "r"(b1));
}

// ===========================================================================
// tf32 tensor-core GEMM (unchanged from R6): Y = X @ W + bias.
// ===========================================================================
#define BKK 32
#define ASTR 36
#define BSTR 136
#define PERBUF (128 * ASTR + BKK * BSTR)
#define GEMM_SMEM (2 * PERBUF * 4)

__device__ __forceinline__ void gemm_tf32_body(
    const float* __restrict__ X, const float* __restrict__ W,
    const float* __restrict__ bias, float* __restrict__ Y, bool split)
{
    extern __shared__ uint32_t smu[];

    const int K = D_MODEL, N = D_MODEL;
    const int m0 = blockIdx.y * 128;
    const int n0 = blockIdx.x * 128;
    const int tid = threadIdx.x;
    const int lane = tid & 31;
    const int wid = tid >> 5;
    const int warpM = wid >> 2;
    const int warpN = wid & 3;
    const int g = lane >> 2;
    const int t = lane & 3;

    const float* xp = X + (size_t)(m0 + (tid >> 3)) * K + (tid & 7) * 4;
    const float* wp = W + (size_t)(tid >> 5) * N + n0 + (tid & 31) * 4;

    const int aOff = (tid >> 3) * ASTR + (tid & 7) * 4;
    const int bOff = (tid >> 5) * BSTR + (tid & 31) * 4;

    float acc[4][4][4];
#pragma unroll
    for (int mt = 0; mt < 4; ++mt)
#pragma unroll
        for (int nt = 0; nt < 4; ++nt)
#pragma unroll
            for (int r = 0; r < 4; ++r) acc[mt][nt][r] = 0.f;

    float4 ra[4], rb[4];

#pragma unroll
    for (int i = 0; i < 4; ++i) {
        ra[i] = *(const float4*)(xp + (size_t)i * 32 * K);
        rb[i] = *(const float4*)(wp + (size_t)i * 8 * N);
    }
    {
        uint32_t* Au = smu;
        uint32_t* Bu = smu + 128 * ASTR;
#pragma unroll
        for (int i = 0; i < 4; ++i) {
            uint32_t* ap = Au + aOff + i * 32 * ASTR;
            uint2 p0 = make_uint2(f2tf(ra[i].x), f2tf(ra[i].y));
            uint2 p1 = make_uint2(f2tf(ra[i].z), f2tf(ra[i].w));
            *(uint2*)(ap + 0) = p0;
            *(uint2*)(ap + 2) = p1;
            uint4 q = make_uint4(f2tf(rb[i].x), f2tf(rb[i].y), f2tf(rb[i].z), f2tf(rb[i].w));
            *(uint4*)(Bu + bOff + i * 8 * BSTR) = q;
        }
    }
    __syncthreads();

    const int NKT = K / BKK;
    for (int kt = 0; kt < NKT; ++kt) {
        if (kt + 1 < NKT) {
#pragma unroll
            for (int i = 0; i < 4; ++i) {
                ra[i] = *(const float4*)(xp + (kt + 1) * BKK + (size_t)i * 32 * K);
                rb[i] = *(const float4*)(wp + ((size_t)(kt + 1) * BKK + i * 8) * N);
            }
        }
        {
            const uint32_t* Au = smu + (kt & 1) * PERBUF;
            const uint32_t* Bu = Au + 128 * ASTR;
            const int mBase = warpM * 64 + g;
            const int nBase = warpN * 32 + g;
#pragma unroll
            for (int ks = 0; ks < 4; ++ks) {
                const int k0 = ks * 8;
                uint32_t af[4][4], bf[4][2];
#pragma unroll
                for (int mt = 0; mt < 4; ++mt) {
                    const uint32_t* base = Au + (mBase + mt * 16) * ASTR + k0 + t;
                    af[mt][0] = base[0];
                    af[mt][1] = base[8 * ASTR];
                    af[mt][2] = base[4];
                    af[mt][3] = base[8 * ASTR + 4];
                }
#pragma unroll
                for (int nt = 0; nt < 4; ++nt) {
                    const uint32_t* base = Bu + (k0 + t) * BSTR + nBase + nt * 8;
                    bf[nt][0] = base[0];
                    bf[nt][1] = base[4 * BSTR];
                }
#pragma unroll
                for (int mt = 0; mt < 4; ++mt)
#pragma unroll
                    for (int nt = 0; nt < 4; ++nt)
                        mma_tf32(acc[mt][nt][0], acc[mt][nt][1], acc[mt][nt][2], acc[mt][nt][3],
                                 af[mt][0], af[mt][1], af[mt][2], af[mt][3],
                                 bf[nt][0], bf[nt][1]);
            }
        }
        if (kt + 1 < NKT) {
            uint32_t* Au = smu + ((kt + 1) & 1) * PERBUF;
            uint32_t* Bu = Au + 128 * ASTR;
#pragma unroll
            for (int i = 0; i < 4; ++i) {
                uint32_t* ap = Au + aOff + i * 32 * ASTR;
                uint2 p0 = make_uint2(f2tf(ra[i].x), f2tf(ra[i].y));
                uint2 p1 = make_uint2(f2tf(ra[i].z), f2tf(ra[i].w));
                *(uint2*)(ap + 0) = p0;
                *(uint2*)(ap + 2) = p1;
                uint4 q = make_uint4(f2tf(rb[i].x), f2tf(rb[i].y), f2tf(rb[i].z), f2tf(rb[i].w));
                *(uint4*)(Bu + bOff + i * 8 * BSTR) = q;
            }
        }
        __syncthreads();
    }

#pragma unroll
    for (int mt = 0; mt < 4; ++mt) {
#pragma unroll
        for (int nt = 0; nt < 4; ++nt) {
            const int m = m0 + warpM * 64 + mt * 16 + g;
            const int n = n0 + warpN * 32 + nt * 8 + 2 * t;
            const float b0v = bias[n], b1v = bias[n + 1];
            float2 lo = make_float2(acc[mt][nt][0] + b0v, acc[mt][nt][1] + b1v);
            float2 hi = make_float2(acc[mt][nt][2] + b0v, acc[mt][nt][3] + b1v);
            if (split) {
                const int h = n >> 6;
                const int d = n & 63;
                const int bb = m >> 11;
                const int sq = m & (SEQ - 1);
                float* y0 = Y + (((size_t)bb * NHEAD + h) * SEQ + sq) * DEPTH + d;
                *(float2*)y0 = lo;
                const int m2 = m + 8;
                const int bb2 = m2 >> 11;
                const int sq2 = m2 & (SEQ - 1);
                float* y1 = Y + (((size_t)bb2 * NHEAD + h) * SEQ + sq2) * DEPTH + d;
                *(float2*)y1 = hi;
            } else {
                *(float2*)&Y[(size_t)m * N + n] = lo;
                *(float2*)&Y[(size_t)(m + 8) * N + n] = hi;
            }
        }
    }
}

__global__ __launch_bounds__(256) void qkv_proj_kernel(
    const float* __restrict__ q, const float* __restrict__ k, const float* __restrict__ v,
    const float* __restrict__ wq, const float* __restrict__ wk, const float* __restrict__ wv,
    const float* __restrict__ bq, const float* __restrict__ bk, const float* __restrict__ bv)
{
    if (blockIdx.z == 0)      gemm_tf32_body(q, wq, bq, g_qh, true);
    else if (blockIdx.z == 1) gemm_tf32_body(k, wk, bk, g_kh, true);
    else                      gemm_tf32_body(v, wv, bv, g_vh, true);
}

__global__ __launch_bounds__(256) void out_proj_kernel(
    const float* __restrict__ wo, const float* __restrict__ bo, float* __restrict__ out)
{
    gemm_tf32_body(g_att, wo, bo, out, false);
}

// ===========================================================================
// tf32 tensor-core flash attention.
// CTA: 128 q-rows x one (b,h). 128 threads = 4 warps; warp owns 32 q-rows
// (2 m-tiles of 16). kv-tiles of 64, 32 iterations. Online softmax in regs.
// Smem (uint32 words):
//   Qs[128][68]  tf32 Q tile               (A-frag bank 4g+t, conflict-free)
//   Ks[64][72]   tf32 K^T tile, [d][kv]    (B-frag bank 8t+g, conflict-free)
//   Vs[64][72]   tf32 V tile,  [kv][d]     (B-frag bank 8t+g, conflict-free)
//   Ps[128][68]  tf32 P tile (per-warp-private rows)
// Total = (8704 + 4608 + 4608 + 8704)*4 = 106496 B -> 2 CTAs/SM.
// ===========================================================================
#define QSTR 68
#define KSTR 72
#define FLASH_SMEM ((128 * QSTR + 64 * KSTR + 64 * KSTR + 128 * QSTR) * 4)

__global__ __launch_bounds__(128) void flash_attn_tf32_kernel(const float* __restrict__ mask)
{
    extern __shared__ uint32_t su[];
    uint32_t* Qs = su;                       // [128][68]
    uint32_t* Ks = su + 128 * QSTR;          // [64][72]  Ks[d][kv]
    uint32_t* Vs = Ks + 64 * KSTR;           // [64][72]  Vs[kv][d]
    uint32_t* Ps = Vs + 64 * KSTR;           // [128][68]

    const int bh = blockIdx.y;               // b*16 + h
    const int q0 = blockIdx.x * 128;
    const float* Qp = g_qh + (size_t)bh * SEQ * DEPTH;
    const float* Kp = g_kh + (size_t)bh * SEQ * DEPTH;
    const float* Vp = g_vh + (size_t)bh * SEQ * DEPTH;

    const int tid = threadIdx.x;
    const int lane = tid & 31;
    const int wid = tid >> 5;                // 0..3
    const int g = lane >> 2;                 // 0..7
    const int t = lane & 3;                  // 0..3
    const int wbase = wid * 32;              // warp's q-row base (local)

    // ---- stage Q once (tf32) ----
#pragma unroll
    for (int rr = 0; rr < 2; ++rr) {
        const int row = (tid >> 1) + rr * 64;
        const float* src = Qp + (size_t)(q0 + row) * DEPTH + (tid & 1) * 32;
        uint32_t* dst = Qs + row * QSTR + (tid & 1) * 32;
#pragma unroll
        for (int i = 0; i < 8; ++i) {
            float4 vq = *(const float4*)(src + i * 4);
            uint4 u = make_uint4(f2tf(vq.x), f2tf(vq.y), f2tf(vq.z), f2tf(vq.w));
            *(uint4*)(dst + i * 4) = u;
        }
    }

    float m_i[4], l_i[4];
#pragma unroll
    for (int i = 0; i < 4; ++i) { m_i[i] = -1e30f; l_i[i] = 0.f; }
    float o[2][8][4];
#pragma unroll
    for (int mt = 0; mt < 2; ++mt)
#pragma unroll
        for (int nt = 0; nt < 8; ++nt)
#pragma unroll
            for (int r = 0; r < 4; ++r) o[mt][nt][r] = 0.f;

    for (int kt = 0; kt < SEQ / 64; ++kt) {
        const int k0g = kt * 64;
        __syncthreads();   // prior iter done reading Ks/Vs

        // K tile -> Ks[d][kv] (transposed), tf32
        {
            const int kvr = tid & 63;
            const int dh = (tid >> 6) * 32;
            const float* kp = Kp + (size_t)(k0g + kvr) * DEPTH + dh;
#pragma unroll
            for (int i = 0; i < 8; ++i) {
                float4 kf = *(const float4*)(kp + i * 4);
                Ks[(dh + i * 4 + 0) * KSTR + kvr] = f2tf(kf.x);
                Ks[(dh + i * 4 + 1) * KSTR + kvr] = f2tf(kf.y);
                Ks[(dh + i * 4 + 2) * KSTR + kvr] = f2tf(kf.z);
                Ks[(dh + i * 4 + 3) * KSTR + kvr] = f2tf(kf.w);
            }
        }
        // V tile -> Vs[kv][d], tf32
        {
            const int kvv = tid >> 1;
            const int dv = (tid & 1) * 32;
            const float* vp = Vp + (size_t)(k0g + kvv) * DEPTH + dv;
            uint32_t* dst = Vs + kvv * KSTR + dv;
#pragma unroll
            for (int i = 0; i < 8; ++i) {
                float4 vf = *(const float4*)(vp + i * 4);
                uint4 u = make_uint4(f2tf(vf.x), f2tf(vf.y), f2tf(vf.z), f2tf(vf.w));
                *(uint4*)(dst + i * 4) = u;
            }
        }
        __syncthreads();

        // ---- S = Q K^T ----
        float s[2][8][4];
#pragma unroll
        for (int mt = 0; mt < 2; ++mt)
#pragma unroll
            for (int nt = 0; nt < 8; ++nt)
#pragma unroll
                for (int r = 0; r < 4; ++r) s[mt][nt][r] = 0.f;

#pragma unroll
        for (int ks = 0; ks < 8; ++ks) {
            const int k0 = ks * 8;
            uint32_t a[2][4];
#pragma unroll
            for (int mt = 0; mt < 2; ++mt) {
                const uint32_t* base = Qs + (wbase + mt * 16 + g) * QSTR + k0 + t;
                a[mt][0] = base[0];
                a[mt][1] = base[8 * QSTR];
                a[mt][2] = base[4];
                a[mt][3] = base[8 * QSTR + 4];
            }
#pragma unroll
            for (int nt = 0; nt < 8; ++nt) {
                const uint32_t* bp = Ks + (k0 + t) * KSTR + nt * 8 + g;
                const uint32_t b0 = bp[0];
                const uint32_t b1 = bp[4 * KSTR];
                mma_tf32(s[0][nt][0], s[0][nt][1], s[0][nt][2], s[0][nt][3],
                         a[0][0], a[0][1], a[0][2], a[0][3], b0, b1);
                mma_tf32(s[1][nt][0], s[1][nt][1], s[1][nt][2], s[1][nt][3],
                         a[1][0], a[1][1], a[1][2], a[1][3], b0, b1);
            }
        }

        // ---- online softmax (per thread: 4 rows, 16 cols each) ----
        const float scale = 0.125f;
#pragma unroll
        for (int mt = 0; mt < 2; ++mt) {
            const int rowA = q0 + wbase + mt * 16 + g;
            const float* mrA = mask + (size_t)rowA * SEQ + k0g + 2 * t;
            const float* mrB = mrA + (size_t)8 * SEQ;
            float mxA = -1e30f, mxB = -1e30f;
#pragma unroll
            for (int nt = 0; nt < 8; ++nt) {
                float2 mA = *(const float2*)(mrA + nt * 8);
                float2 mB = *(const float2*)(mrB + nt * 8);
                s[mt][nt][0] = s[mt][nt][0] * scale - 1e9f * mA.x;
                s[mt][nt][1] = s[mt][nt][1] * scale - 1e9f * mA.y;
                s[mt][nt][2] = s[mt][nt][2] * scale - 1e9f * mB.x;
                s[mt][nt][3] = s[mt][nt][3] * scale - 1e9f * mB.y;
                mxA = fmaxf(mxA, fmaxf(s[mt][nt][0], s[mt][nt][1]));
                mxB = fmaxf(mxB, fmaxf(s[mt][nt][2], s[mt][nt][3]));
            }
            mxA = fmaxf(mxA, __shfl_xor_sync(0xffffffffu, mxA, 1));
            mxA = fmaxf(mxA, __shfl_xor_sync(0xffffffffu, mxA, 2));
            mxB = fmaxf(mxB, __shfl_xor_sync(0xffffffffu, mxB, 1));
            mxB = fmaxf(mxB, __shfl_xor_sync(0xffffffffu, mxB, 2));

            const float mnA = fmaxf(m_i[2 * mt + 0], mxA);
            const float mnB = fmaxf(m_i[2 * mt + 1], mxB);
            const float corrA = __expf(m_i[2 * mt + 0] - mnA);
            const float corrB = __expf(m_i[2 * mt + 1] - mnB);
            m_i[2 * mt + 0] = mnA;
            m_i[2 * mt + 1] = mnB;

            float rsA = 0.f, rsB = 0.f;
#pragma unroll
            for (int nt = 0; nt < 8; ++nt) {
                s[mt][nt][0] = __expf(s[mt][nt][0] - mnA);
                s[mt][nt][1] = __expf(s[mt][nt][1] - mnA);
                s[mt][nt][2] = __expf(s[mt][nt][2] - mnB);
                s[mt][nt][3] = __expf(s[mt][nt][3] - mnB);
                rsA += s[mt][nt][0] + s[mt][nt][1];
                rsB += s[mt][nt][2] + s[mt][nt][3];
            }
            rsA += __shfl_xor_sync(0xffffffffu, rsA, 1);
            rsA += __shfl_xor_sync(0xffffffffu, rsA, 2);
            rsB += __shfl_xor_sync(0xffffffffu, rsB, 1);
            rsB += __shfl_xor_sync(0xffffffffu, rsB, 2);

            l_i[2 * mt + 0] = l_i[2 * mt + 0] * corrA + rsA;
            l_i[2 * mt + 1] = l_i[2 * mt + 1] * corrB + rsB;
#pragma unroll
            for (int nt = 0; nt < 8; ++nt) {
                o[mt][nt][0] *= corrA;
                o[mt][nt][1] *= corrA;
                o[mt][nt][2] *= corrB;
                o[mt][nt][3] *= corrB;
            }
        }

        // ---- P -> smem (tf32), per-warp-private rows ----
#pragma unroll
        for (int mt = 0; mt < 2; ++mt) {
            uint32_t* prA = Ps + (wbase + mt * 16 + g) * QSTR + 2 * t;
            uint32_t* prB = prA + 8 * QSTR;
#pragma unroll
            for (int nt = 0; nt < 8; ++nt) {
                *(uint2*)(prA + nt * 8) = make_uint2(f2tf(s[mt][nt][0]), f2tf(s[mt][nt][1]));
                *(uint2*)(prB + nt * 8) = make_uint2(f2tf(s[mt][nt][2]), f2tf(s[mt][nt][3]));
            }
        }
        __syncwarp();

        // ---- O += P V ----
#pragma unroll
        for (int ks = 0; ks < 8; ++ks) {
            const int k0 = ks * 8;
            uint32_t a[2][4];
#pragma unroll
            for (int mt = 0; mt < 2; ++mt) {
                const uint32_t* base = Ps + (wbase + mt * 16 + g) * QSTR + k0 + t;
                a[mt][0] = base[0];
                a[mt][1] = base[8 * QSTR];
                a[mt][2] = base[4];
                a[mt][3] = base[8 * QSTR + 4];
            }
#pragma unroll
            for (int nt = 0; nt < 8; ++nt) {
                const uint32_t* bp = Vs + (k0 + t) * KSTR + nt * 8 + g;
                const uint32_t b0 = bp[0];
                const uint32_t b1 = bp[4 * KSTR];
                mma_tf32(o[0][nt][0], o[0][nt][1], o[0][nt][2], o[0][nt][3],
                         a[0][0], a[0][1], a[0][2], a[0][3], b0, b1);
                mma_tf32(o[1][nt][0], o[1][nt][1], o[1][nt][2], o[1][nt][3],
                         a[1][0], a[1][1], a[1][2], a[1][3], b0, b1);
            }
        }
    }

    // ---- epilogue: normalize + write merged-head layout [B,S,1024] ----
    const int bb2 = bh >> 4;
    const int h = bh & 15;
#pragma unroll
    for (int mt = 0; mt < 2; ++mt) {
        const float invA = 1.f / l_i[2 * mt + 0];
        const float invB = 1.f / l_i[2 * mt + 1];
        const int rowA = q0 + wbase + mt * 16 + g;
        float* oA = g_att + ((size_t)bb2 * SEQ + rowA) * D_MODEL + h * DEPTH + 2 * t;
        float* oB = oA + (size_t)8 * D_MODEL;
#pragma unroll
        for (int nt = 0; nt < 8; ++nt) {
            *(float2*)(oA + nt * 8) = make_float2(o[mt][nt][0] * invA, o[mt][nt][1] * invA);
            *(float2*)(oB + nt * 8) = make_float2(o[mt][nt][2] * invB, o[mt][nt][3] * invB);
        }
    }
}

// ---------------------------------------------------------------------------
extern "C" void kernel_launch(void* const* d_in, const int* in_sizes, int n_in,
                              void* d_out, int out_size)
{
    const float* q    = (const float*)d_in[0];
    const float* k    = (const float*)d_in[1];
    const float* v    = (const float*)d_in[2];
    const float* mask = (const float*)d_in[3];
    const float* wq   = (const float*)d_in[4];
    const float* bq   = (const float*)d_in[5];
    const float* wk   = (const float*)d_in[6];
    const float* bk   = (const float*)d_in[7];
    const float* wv   = (const float*)d_in[8];
    const float* bv   = (const float*)d_in[9];
    const float* wo   = (const float*)d_in[10];
    const float* bo   = (const float*)d_in[11];
    float* out = (float*)d_out;

    (void)in_sizes; (void)n_in; (void)out_size;

    cudaFuncSetAttribute(qkv_proj_kernel,
                         cudaFuncAttributeMaxDynamicSharedMemorySize, GEMM_SMEM);
    cudaFuncSetAttribute(out_proj_kernel,
                         cudaFuncAttributeMaxDynamicSharedMemorySize, GEMM_SMEM);
    cudaFuncSetAttribute(flash_attn_tf32_kernel,
                         cudaFuncAttributeMaxDynamicSharedMemorySize, FLASH_SMEM);

    dim3 gproj(D_MODEL / 128, MTOT / 128, 3);
    qkv_proj_kernel<<<gproj, 256, GEMM_SMEM>>>(q, k, v, wq, wk, wv, bq, bk, bv);

    flash_attn_tf32_kernel<<<dim3(SEQ / 128, BB * NHEAD), 128, FLASH_SMEM>>>(mask);

    out_proj_kernel<<<dim3(D_MODEL / 128, MTOT / 128), 256, GEMM_SMEM>>>(wo, bo, out);
}

// round 13
// speedup vs baseline: 3.2259x; 1.2245x over previous
#include <cuda_runtime.h>
#include <cstdint>

#define D_MODEL 1024
#define NHEAD 16
#define DEPTH 64
#define BB 2
#define SEQ 2048
#define MTOT (BB * SEQ)  // 4096

// Scratch (allocation-free rule: __device__ globals)
__device__ float g_qh[(size_t)BB * NHEAD * SEQ * DEPTH];  // [B,H,S,64]  (tf32-rounded)
__device__ float g_kh[(size_t)BB * NHEAD * DEPTH * SEQ];  // [B,H,64,S]  TRANSPOSED (tf32-rounded)
__device__ float g_vh[(size_t)BB * NHEAD * SEQ * DEPTH];  // [B,H,S,64]  (tf32-rounded)
__device__ float g_att[(size_t)MTOT * D_MODEL];           // [B,S,1024] merged heads

__device__ __forceinline__ uint32_t f2tf(float f) {
    uint32_t u;
    asm("cvt.rna.tf32.f32 %0, %1;" : "=r"(u) : "f"(f));
    return u;
}

__device__ __forceinline__ void mma_tf32(float& c0, float& c1, float& c2, float& c3,
                                         uint32_t a0, uint32_t a1, uint32_t a2, uint32_t a3,
                                         uint32_t b0, uint32_t b1) {
    asm("mma.sync.aligned.m16n8k8.row.col.f32.tf32.tf32.f32 "
        "{%0,%1,%2,%3},{%4,%5,%6,%7},{%8,%9},{%0,%1,%2,%3};"
        : "+f"(c0), "+f"(c1), "+f"(c2), "+f"(c3)
        : "r"(a0), "r"(a1), "r"(a2), "r"(a3), "r"(b0), "r"(b1));
}

__device__ __forceinline__ uint32_t s2u(const void* p) {
    return (uint32_t)__cvta_generic_to_shared(p);
}
#define CP16(dst_u32, src_ptr) \
    asm volatile("cp.async.ca.shared.global [%0], [%1], 16;" :: "r"(dst_u32), "l"(src_ptr) : "memory")
#define CPCOMMIT() asm volatile("cp.async.commit_group;" ::: "memory")
#define CPWAIT1()  asm volatile("cp.async.wait_group 1;" ::: "memory")

// ===========================================================================
// tf32 tensor-core GEMM: Y = X @ W + bias.  M=4096, N=K=1024.
// MODE 0: plain row-major [M,N] fp32 out (final output)
// MODE 1: head-split [B,H,S,64], tf32-pre-rounded (Q, V)
// MODE 2: head-split TRANSPOSED [B,H,64,S], tf32-pre-rounded (K)
// ===========================================================================
#define BKK 32
#define ASTR 36
#define BSTR 136
#define PERBUF (128 * ASTR + BKK * BSTR)
#define GEMM_SMEM (2 * PERBUF * 4)

template <int MODE>
__device__ __forceinline__ void gemm_tf32_body(
    const float* __restrict__ X, const float* __restrict__ W,
    const float* __restrict__ bias, float* __restrict__ Y)
{
    extern __shared__ uint32_t smu[];

    const int K = D_MODEL, N = D_MODEL;
    const int m0 = blockIdx.y * 128;
    const int n0 = blockIdx.x * 128;
    const int tid = threadIdx.x;
    const int lane = tid & 31;
    const int wid = tid >> 5;
    const int warpM = wid >> 2;
    const int warpN = wid & 3;
    const int g = lane >> 2;
    const int t = lane & 3;

    const float* xp = X + (size_t)(m0 + (tid >> 3)) * K + (tid & 7) * 4;
    const float* wp = W + (size_t)(tid >> 5) * N + n0 + (tid & 31) * 4;

    const int aOff = (tid >> 3) * ASTR + (tid & 7) * 4;
    const int bOff = (tid >> 5) * BSTR + (tid & 31) * 4;

    float acc[4][4][4];
#pragma unroll
    for (int mt = 0; mt < 4; ++mt)
#pragma unroll
        for (int nt = 0; nt < 4; ++nt)
#pragma unroll
            for (int r = 0; r < 4; ++r) acc[mt][nt][r] = 0.f;

    float4 ra[4], rb[4];

#pragma unroll
    for (int i = 0; i < 4; ++i) {
        ra[i] = *(const float4*)(xp + (size_t)i * 32 * K);
        rb[i] = *(const float4*)(wp + (size_t)i * 8 * N);
    }
    {
        uint32_t* Au = smu;
        uint32_t* Bu = smu + 128 * ASTR;
#pragma unroll
        for (int i = 0; i < 4; ++i) {
            uint32_t* ap = Au + aOff + i * 32 * ASTR;
            uint2 p0 = make_uint2(f2tf(ra[i].x), f2tf(ra[i].y));
            uint2 p1 = make_uint2(f2tf(ra[i].z), f2tf(ra[i].w));
            *(uint2*)(ap + 0) = p0;
            *(uint2*)(ap + 2) = p1;
            uint4 q = make_uint4(f2tf(rb[i].x), f2tf(rb[i].y), f2tf(rb[i].z), f2tf(rb[i].w));
            *(uint4*)(Bu + bOff + i * 8 * BSTR) = q;
        }
    }
    __syncthreads();

    const int NKT = K / BKK;
    for (int kt = 0; kt < NKT; ++kt) {
        if (kt + 1 < NKT) {
#pragma unroll
            for (int i = 0; i < 4; ++i) {
                ra[i] = *(const float4*)(xp + (kt + 1) * BKK + (size_t)i * 32 * K);
                rb[i] = *(const float4*)(wp + ((size_t)(kt + 1) * BKK + i * 8) * N);
            }
        }
        {
            const uint32_t* Au = smu + (kt & 1) * PERBUF;
            const uint32_t* Bu = Au + 128 * ASTR;
            const int mBase = warpM * 64 + g;
            const int nBase = warpN * 32 + g;
#pragma unroll
            for (int ks = 0; ks < 4; ++ks) {
                const int k0 = ks * 8;
                uint32_t af[4][4], bf[4][2];
#pragma unroll
                for (int mt = 0; mt < 4; ++mt) {
                    const uint32_t* base = Au + (mBase + mt * 16) * ASTR + k0 + t;
                    af[mt][0] = base[0];
                    af[mt][1] = base[8 * ASTR];
                    af[mt][2] = base[4];
                    af[mt][3] = base[8 * ASTR + 4];
                }
#pragma unroll
                for (int nt = 0; nt < 4; ++nt) {
                    const uint32_t* base = Bu + (k0 + t) * BSTR + nBase + nt * 8;
                    bf[nt][0] = base[0];
                    bf[nt][1] = base[4 * BSTR];
                }
#pragma unroll
                for (int mt = 0; mt < 4; ++mt)
#pragma unroll
                    for (int nt = 0; nt < 4; ++nt)
                        mma_tf32(acc[mt][nt][0], acc[mt][nt][1], acc[mt][nt][2], acc[mt][nt][3],
                                 af[mt][0], af[mt][1], af[mt][2], af[mt][3],
                                 bf[nt][0], bf[nt][1]);
            }
        }
        if (kt + 1 < NKT) {
            uint32_t* Au = smu + ((kt + 1) & 1) * PERBUF;
            uint32_t* Bu = Au + 128 * ASTR;
#pragma unroll
            for (int i = 0; i < 4; ++i) {
                uint32_t* ap = Au + aOff + i * 32 * ASTR;
                uint2 p0 = make_uint2(f2tf(ra[i].x), f2tf(ra[i].y));
                uint2 p1 = make_uint2(f2tf(ra[i].z), f2tf(ra[i].w));
                *(uint2*)(ap + 0) = p0;
                *(uint2*)(ap + 2) = p1;
                uint4 q = make_uint4(f2tf(rb[i].x), f2tf(rb[i].y), f2tf(rb[i].z), f2tf(rb[i].w));
                *(uint4*)(Bu + bOff + i * 8 * BSTR) = q;
            }
        }
        __syncthreads();
    }

#pragma unroll
    for (int mt = 0; mt < 4; ++mt) {
#pragma unroll
        for (int nt = 0; nt < 4; ++nt) {
            const int m = m0 + warpM * 64 + mt * 16 + g;
            const int n = n0 + warpN * 32 + nt * 8 + 2 * t;
            const float b0v = bias[n], b1v = bias[n + 1];
            const float v0 = acc[mt][nt][0] + b0v;
            const float v1 = acc[mt][nt][1] + b1v;
            const float v2 = acc[mt][nt][2] + b0v;
            const float v3 = acc[mt][nt][3] + b1v;
            if (MODE == 0) {
                *(float2*)&Y[(size_t)m * N + n] = make_float2(v0, v1);
                *(float2*)&Y[(size_t)(m + 8) * N + n] = make_float2(v2, v3);
            } else if (MODE == 1) {
                const int h = n >> 6;
                const int d = n & 63;
                const int bb = m >> 11;
                const int sq = m & (SEQ - 1);
                const int m2 = m + 8;
                const int bb2 = m2 >> 11;
                const int sq2 = m2 & (SEQ - 1);
                float2 lo = make_float2(__uint_as_float(f2tf(v0)), __uint_as_float(f2tf(v1)));
                float2 hi = make_float2(__uint_as_float(f2tf(v2)), __uint_as_float(f2tf(v3)));
                *(float2*)(Y + (((size_t)bb * NHEAD + h) * SEQ + sq) * DEPTH + d) = lo;
                *(float2*)(Y + (((size_t)bb2 * NHEAD + h) * SEQ + sq2) * DEPTH + d) = hi;
            } else {
                // MODE 2: K transposed [B,H,64,S]
                const int h = n >> 6;
                const int d = n & 63;
                const int bb = m >> 11;
                const int sq = m & (SEQ - 1);
                const int m2 = m + 8;
                const int bb2 = m2 >> 11;
                const int sq2 = m2 & (SEQ - 1);
                const size_t base = ((size_t)bb * NHEAD + h) * DEPTH * SEQ;
                const size_t base2 = ((size_t)bb2 * NHEAD + h) * DEPTH * SEQ;
                Y[base + (size_t)d * SEQ + sq]        = __uint_as_float(f2tf(v0));
                Y[base + (size_t)(d + 1) * SEQ + sq]  = __uint_as_float(f2tf(v1));
                Y[base2 + (size_t)d * SEQ + sq2]       = __uint_as_float(f2tf(v2));
                Y[base2 + (size_t)(d + 1) * SEQ + sq2] = __uint_as_float(f2tf(v3));
            }
        }
    }
}

__global__ __launch_bounds__(256) void qkv_proj_kernel(
    const float* __restrict__ q, const float* __restrict__ k, const float* __restrict__ v,
    const float* __restrict__ wq, const float* __restrict__ wk, const float* __restrict__ wv,
    const float* __restrict__ bq, const float* __restrict__ bk, const float* __restrict__ bv)
{
    if (blockIdx.z == 0)      gemm_tf32_body<1>(q, wq, bq, g_qh);
    else if (blockIdx.z == 1) gemm_tf32_body<2>(k, wk, bk, g_kh);
    else                      gemm_tf32_body<1>(v, wv, bv, g_vh);
}

__global__ __launch_bounds__(256) void out_proj_kernel(
    const float* __restrict__ wo, const float* __restrict__ bo, float* __restrict__ out)
{
    gemm_tf32_body<0>(g_att, wo, bo, out);
}

// ===========================================================================
// tf32 tensor-core flash attention, cp.async double-buffered.
// CTA: 128 q-rows x one (b,h). 128 threads = 4 warps; warp owns 32 q-rows
// (2 m-tiles of 16). kv-tiles of 64, 32 iterations.
// K arrives pre-transposed [d][s] and pre-rounded -> straight cp.async copy.
// P never touches smem: C-frag -> A-frag via quad shuffles.
// Smem (words): Qs 128x68 | K0 64x72 | K1 | V0 64x72 | V1 = 27136 w = 108544 B
//   -> 2 CTAs/SM.
// ===========================================================================
#define QSTR 68
#define KSTR 72
#define KVWORDS (64 * KSTR)  // 4608
#define FLASH_SMEM ((128 * QSTR + 4 * KVWORDS) * 4)   // 108544

__global__ __launch_bounds__(128, 2) void flash_attn_tf32_kernel(const float* __restrict__ mask)
{
    extern __shared__ uint32_t su[];
    uint32_t* Qs = su;                                   // [128][68]
    uint32_t* Kb0 = su + 128 * QSTR;                     // [64][72]  [d][kv]
    uint32_t* Kb1 = Kb0 + KVWORDS;
    uint32_t* Vb0 = Kb1 + KVWORDS;                       // [64][72]  [kv][d]
    uint32_t* Vb1 = Vb0 + KVWORDS;

    const int bh = blockIdx.y;               // b*16 + h
    const int q0 = blockIdx.x * 128;
    const float* Qp = g_qh + ((size_t)bh * SEQ + q0) * DEPTH;
    const float* KpT = g_kh + (size_t)bh * DEPTH * SEQ;   // transposed [64][SEQ]
    const float* Vp = g_vh + (size_t)bh * SEQ * DEPTH;

    const int tid = threadIdx.x;
    const int lane = tid & 31;
    const int wid = tid >> 5;                // 0..3
    const int g = lane >> 2;                 // 0..7
    const int t = lane & 3;                  // 0..3
    const int wbase = wid * 32;              // warp's q-row base (local)
    const int srcA = (lane & ~3) | (t >> 1); // quad-lane for P col t
    const int srcB = srcA + 2;               // quad-lane for P col t+4

    // ---- prologue: stage Q + tile0 (group0), tile1 (group1) ----
    {
        const int r0 = tid >> 4, c0 = (tid & 15) * 4;
#pragma unroll
        for (int i = 0; i < 16; ++i) {
            const int r = r0 + i * 8;
            CP16(s2u(Qs + r * QSTR + c0), Qp + (size_t)r * DEPTH + c0);
        }
#pragma unroll
        for (int i = 0; i < 8; ++i) {
            const int r = r0 + i * 8;
            CP16(s2u(Kb0 + r * KSTR + c0), KpT + (size_t)r * SEQ + 0 + c0);
            CP16(s2u(Vb0 + r * KSTR + c0), Vp + (size_t)(0 + r) * DEPTH + c0);
        }
        CPCOMMIT();
#pragma unroll
        for (int i = 0; i < 8; ++i) {
            const int r = r0 + i * 8;
            CP16(s2u(Kb1 + r * KSTR + c0), KpT + (size_t)r * SEQ + 64 + c0);
            CP16(s2u(Vb1 + r * KSTR + c0), Vp + (size_t)(64 + r) * DEPTH + c0);
        }
        CPCOMMIT();
    }

    float m_i[4], l_i[4];
#pragma unroll
    for (int i = 0; i < 4; ++i) { m_i[i] = -1e30f; l_i[i] = 0.f; }
    float o[2][8][4];
#pragma unroll
    for (int mt = 0; mt < 2; ++mt)
#pragma unroll
        for (int nt = 0; nt < 8; ++nt)
#pragma unroll
            for (int r = 0; r < 4; ++r) o[mt][nt][r] = 0.f;

    const int NT = SEQ / 64;  // 32
    for (int kt = 0; kt < NT; ++kt) {
        const int k0g = kt * 64;
        CPWAIT1();
        __syncthreads();   // tile kt resident; prior readers of this buf done

        const uint32_t* Ks = (kt & 1) ? Kb1 : Kb0;
        const uint32_t* Vs = (kt & 1) ? Vb1 : Vb0;

        // ---- mask prefetch (issued before MMAs, consumed in softmax) ----
        float2 mk[2][8][2];
#pragma unroll
        for (int mt = 0; mt < 2; ++mt) {
            const float* mrA = mask + (size_t)(q0 + wbase + mt * 16 + g) * SEQ + k0g + 2 * t;
            const float* mrB = mrA + (size_t)8 * SEQ;
#pragma unroll
            for (int nt = 0; nt < 8; ++nt) {
                mk[mt][nt][0] = *(const float2*)(mrA + nt * 8);
                mk[mt][nt][1] = *(const float2*)(mrB + nt * 8);
            }
        }

        // ---- S = Q K^T ----
        float s[2][8][4];
#pragma unroll
        for (int mt = 0; mt < 2; ++mt)
#pragma unroll
            for (int nt = 0; nt < 8; ++nt)
#pragma unroll
                for (int r = 0; r < 4; ++r) s[mt][nt][r] = 0.f;

#pragma unroll
        for (int ks = 0; ks < 8; ++ks) {
            const int k0 = ks * 8;
            uint32_t a[2][4];
#pragma unroll
            for (int mt = 0; mt < 2; ++mt) {
                const uint32_t* base = Qs + (wbase + mt * 16 + g) * QSTR + k0 + t;
                a[mt][0] = base[0];
                a[mt][1] = base[8 * QSTR];
                a[mt][2] = base[4];
                a[mt][3] = base[8 * QSTR + 4];
            }
#pragma unroll
            for (int nt = 0; nt < 8; ++nt) {
                const uint32_t* bp = Ks + (k0 + t) * KSTR + nt * 8 + g;
                const uint32_t b0 = bp[0];
                const uint32_t b1 = bp[4 * KSTR];
                mma_tf32(s[0][nt][0], s[0][nt][1], s[0][nt][2], s[0][nt][3],
                         a[0][0], a[0][1], a[0][2], a[0][3], b0, b1);
                mma_tf32(s[1][nt][0], s[1][nt][1], s[1][nt][2], s[1][nt][3],
                         a[1][0], a[1][1], a[1][2], a[1][3], b0, b1);
            }
        }

        // ---- online softmax (per thread: 4 rows, 16 cols each) ----
        const float scale = 0.125f;
#pragma unroll
        for (int mt = 0; mt < 2; ++mt) {
            float mxA = -1e30f, mxB = -1e30f;
#pragma unroll
            for (int nt = 0; nt < 8; ++nt) {
                s[mt][nt][0] = s[mt][nt][0] * scale - 1e9f * mk[mt][nt][0].x;
                s[mt][nt][1] = s[mt][nt][1] * scale - 1e9f * mk[mt][nt][0].y;
                s[mt][nt][2] = s[mt][nt][2] * scale - 1e9f * mk[mt][nt][1].x;
                s[mt][nt][3] = s[mt][nt][3] * scale - 1e9f * mk[mt][nt][1].y;
                mxA = fmaxf(mxA, fmaxf(s[mt][nt][0], s[mt][nt][1]));
                mxB = fmaxf(mxB, fmaxf(s[mt][nt][2], s[mt][nt][3]));
            }
            mxA = fmaxf(mxA, __shfl_xor_sync(0xffffffffu, mxA, 1));
            mxA = fmaxf(mxA, __shfl_xor_sync(0xffffffffu, mxA, 2));
            mxB = fmaxf(mxB, __shfl_xor_sync(0xffffffffu, mxB, 1));
            mxB = fmaxf(mxB, __shfl_xor_sync(0xffffffffu, mxB, 2));

            const float mnA = fmaxf(m_i[2 * mt + 0], mxA);
            const float mnB = fmaxf(m_i[2 * mt + 1], mxB);
            const float corrA = __expf(m_i[2 * mt + 0] - mnA);
            const float corrB = __expf(m_i[2 * mt + 1] - mnB);
            m_i[2 * mt + 0] = mnA;
            m_i[2 * mt + 1] = mnB;

            float rsA = 0.f, rsB = 0.f;
#pragma unroll
            for (int nt = 0; nt < 8; ++nt) {
                s[mt][nt][0] = __expf(s[mt][nt][0] - mnA);
                s[mt][nt][1] = __expf(s[mt][nt][1] - mnA);
                s[mt][nt][2] = __expf(s[mt][nt][2] - mnB);
                s[mt][nt][3] = __expf(s[mt][nt][3] - mnB);
                rsA += s[mt][nt][0] + s[mt][nt][1];
                rsB += s[mt][nt][2] + s[mt][nt][3];
            }
            rsA += __shfl_xor_sync(0xffffffffu, rsA, 1);
            rsA += __shfl_xor_sync(0xffffffffu, rsA, 2);
            rsB += __shfl_xor_sync(0xffffffffu, rsB, 1);
            rsB += __shfl_xor_sync(0xffffffffu, rsB, 2);

            l_i[2 * mt + 0] = l_i[2 * mt + 0] * corrA + rsA;
            l_i[2 * mt + 1] = l_i[2 * mt + 1] * corrB + rsB;
#pragma unroll
            for (int nt = 0; nt < 8; ++nt) {
                o[mt][nt][0] *= corrA;
                o[mt][nt][1] *= corrA;
                o[mt][nt][2] *= corrB;
                o[mt][nt][3] *= corrB;
            }
        }

        // ---- O += P V.  P: C-frag -> A-frag via quad shuffles (no smem) ----
        // C-frag: thread(g,t) holds P[g][8ks+2t], P[g][8ks+2t+1], P[g+8][...], P[g+8][...]
        // A-frag needs P[g][8ks+t], P[g+8][8ks+t], P[g][8ks+t+4], P[g+8][8ks+t+4]
#pragma unroll
        for (int ks = 0; ks < 8; ++ks) {
            const int k0 = ks * 8;
            uint32_t a[2][4];
#pragma unroll
            for (int mt = 0; mt < 2; ++mt) {
                float e0, e1;
                e0 = __shfl_sync(0xffffffffu, s[mt][ks][0], srcA);
                e1 = __shfl_sync(0xffffffffu, s[mt][ks][1], srcA);
                const float v0 = (t & 1) ? e1 : e0;                 // P[g][k0+t]
                e0 = __shfl_sync(0xffffffffu, s[mt][ks][2], srcA);
                e1 = __shfl_sync(0xffffffffu, s[mt][ks][3], srcA);
                const float v1 = (t & 1) ? e1 : e0;                 // P[g+8][k0+t]
                e0 = __shfl_sync(0xffffffffu, s[mt][ks][0], srcB);
                e1 = __shfl_sync(0xffffffffu, s[mt][ks][1], srcB);
                const float v2 = (t & 1) ? e1 : e0;                 // P[g][k0+t+4]
                e0 = __shfl_sync(0xffffffffu, s[mt][ks][2], srcB);
                e1 = __shfl_sync(0xffffffffu, s[mt][ks][3], srcB);
                const float v3 = (t & 1) ? e1 : e0;                 // P[g+8][k0+t+4]
                a[mt][0] = f2tf(v0);
                a[mt][1] = f2tf(v1);
                a[mt][2] = f2tf(v2);
                a[mt][3] = f2tf(v3);
            }
#pragma unroll
            for (int nt = 0; nt < 8; ++nt) {
                const uint32_t* bp = Vs + (k0 + t) * KSTR + nt * 8 + g;
                const uint32_t b0 = bp[0];
                const uint32_t b1 = bp[4 * KSTR];
                mma_tf32(o[0][nt][0], o[0][nt][1], o[0][nt][2], o[0][nt][3],
                         a[0][0], a[0][1], a[0][2], a[0][3], b0, b1);
                mma_tf32(o[1][nt][0], o[1][nt][1], o[1][nt][2], o[1][nt][3],
                         a[1][0], a[1][1], a[1][2], a[1][3], b0, b1);
            }
        }

        __syncthreads();   // all warps done reading buf (kt&1) before refill

        // ---- stage tile kt+2 into buf (kt&1) ----
        if (kt + 2 < NT) {
            const int k2 = (kt + 2) * 64;
            uint32_t* Kd = (kt & 1) ? Kb1 : Kb0;
            uint32_t* Vd = (kt & 1) ? Vb1 : Vb0;
            const int r0 = tid >> 4, c0 = (tid & 15) * 4;
#pragma unroll
            for (int i = 0; i < 8; ++i) {
                const int r = r0 + i * 8;
                CP16(s2u(Kd + r * KSTR + c0), KpT + (size_t)r * SEQ + k2 + c0);
                CP16(s2u(Vd + r * KSTR + c0), Vp + (size_t)(k2 + r) * DEPTH + c0);
            }
        }
        CPCOMMIT();   // always commit (possibly empty) to keep wait accounting
    }

    // ---- epilogue: normalize + write merged-head layout [B,S,1024] ----
    const int bb2 = bh >> 4;
    const int h = bh & 15;
#pragma unroll
    for (int mt = 0; mt < 2; ++mt) {
        const float invA = 1.f / l_i[2 * mt + 0];
        const float invB = 1.f / l_i[2 * mt + 1];
        const int rowA = q0 + wbase + mt * 16 + g;
        float* oA = g_att + ((size_t)bb2 * SEQ + rowA) * D_MODEL + h * DEPTH + 2 * t;
        float* oB = oA + (size_t)8 * D_MODEL;
#pragma unroll
        for (int nt = 0; nt < 8; ++nt) {
            *(float2*)(oA + nt * 8) = make_float2(o[mt][nt][0] * invA, o[mt][nt][1] * invA);
            *(float2*)(oB + nt * 8) = make_float2(o[mt][nt][2] * invB, o[mt][nt][3] * invB);
        }
    }
}

// ---------------------------------------------------------------------------
extern "C" void kernel_launch(void* const* d_in, const int* in_sizes, int n_in,
                              void* d_out, int out_size)
{
    const float* q    = (const float*)d_in[0];
    const float* k    = (const float*)d_in[1];
    const float* v    = (const float*)d_in[2];
    const float* mask = (const float*)d_in[3];
    const float* wq   = (const float*)d_in[4];
    const float* bq   = (const float*)d_in[5];
    const float* wk   = (const float*)d_in[6];
    const float* bk   = (const float*)d_in[7];
    const float* wv   = (const float*)d_in[8];
    const float* bv   = (const float*)d_in[9];
    const float* wo   = (const float*)d_in[10];
    const float* bo   = (const float*)d_in[11];
    float* out = (float*)d_out;

    (void)in_sizes; (void)n_in; (void)out_size;

    cudaFuncSetAttribute(qkv_proj_kernel,
                         cudaFuncAttributeMaxDynamicSharedMemorySize, GEMM_SMEM);
    cudaFuncSetAttribute(out_proj_kernel,
                         cudaFuncAttributeMaxDynamicSharedMemorySize, GEMM_SMEM);
    cudaFuncSetAttribute(flash_attn_tf32_kernel,
                         cudaFuncAttributeMaxDynamicSharedMemorySize, FLASH_SMEM);

    dim3 gproj(D_MODEL / 128, MTOT / 128, 3);
    qkv_proj_kernel<<<gproj, 256, GEMM_SMEM>>>(q, k, v, wq, wk, wv, bq, bk, bv);

    flash_attn_tf32_kernel<<<dim3(SEQ / 128, BB * NHEAD), 128, FLASH_SMEM>>>(mask);

    out_proj_kernel<<<dim3(D_MODEL / 128, MTOT / 128), 256, GEMM_SMEM>>>(wo, bo, out);
}